// round 3
// baseline (speedup 1.0000x reference)
#include <cuda_runtime.h>
#include <stdint.h>

// Problem constants (fixed by the reference)
#define NXD   432
#define NYD   496
#define BD    4
#define CD    64
#define PLANE (NXD * NYD)        // 214272  (divisible by 4)
#define NBINS 3
#define NPIL  64000              // B * P_PER per bin
#define NBB   (NBINS * BD)       // 12 (bin,b) canvases

// Scratch: pillar-index canvas, -1 = empty. 12 * 214272 * 4B ~= 10.3 MB.
__device__ int g_idx[NBB * PLANE];

// ---------------------------------------------------------------------------
// Kernel 1: fill index canvas with -1 (vectorized int4 stores)
// ---------------------------------------------------------------------------
__global__ void init_idx_kernel() {
    const int n4 = (NBB * PLANE) / 4;
    int t = blockIdx.x * blockDim.x + threadIdx.x;
    if (t < n4) {
        reinterpret_cast<int4*>(g_idx)[t] = make_int4(-1, -1, -1, -1);
    }
}

// ---------------------------------------------------------------------------
// Kernel 2: scatter pillar indices into the canvas.
// coords row layout: [b, z, y, x]; local = z + y*NX + x  (nz == 1)
// ---------------------------------------------------------------------------
__global__ void scatter_idx_kernel(const int* __restrict__ c0,
                                   const int* __restrict__ c1,
                                   const int* __restrict__ c2) {
    int t = blockIdx.x * blockDim.x + threadIdx.x;
    if (t >= NBINS * NPIL) return;
    int bin = t / NPIL;
    int p   = t - bin * NPIL;
    const int* cbase = (bin == 0) ? c0 : (bin == 1) ? c1 : c2;
    // int4 load of the coord row (rows are 16B, base is 16B aligned)
    int4 cr = reinterpret_cast<const int4*>(cbase)[p];
    int b = cr.x, z = cr.y, y = cr.z, x = cr.w;
    int local = z + y * NXD + x;
    g_idx[(bin * BD + b) * PLANE + local] = p;
}

// ---------------------------------------------------------------------------
// Kernel 3: gather. Each thread owns 4 consecutive positions of one (bin,b)
// canvas and writes all 64 channels with float4 stores (coalesced across the
// warp: 32 threads * 16B = 512B contiguous per channel iteration).
// Empty cells (the common case, ~92.5%) take a zero-fill fast path.
// ---------------------------------------------------------------------------
__global__ void gather_kernel(const float* __restrict__ p0,
                              const float* __restrict__ p1,
                              const float* __restrict__ p2,
                              float* __restrict__ out) {
    const int Q = PLANE / 4;               // 53568 position-groups per canvas
    int t  = blockIdx.x * blockDim.x + threadIdx.x;
    int bb = blockIdx.y;                   // 0..11 = bin*4 + b
    if (t >= Q) return;
    int pos = t * 4;
    int bin = bb >> 2;
    const float* pil = (bin == 0) ? p0 : (bin == 1) ? p1 : p2;

    int4 pidx = *reinterpret_cast<const int4*>(g_idx + (size_t)bb * PLANE + pos);
    float* outp = out + (size_t)bb * CD * PLANE + pos;

    // All four empty <=> AND of the four has sign bit set (-1 is all-ones;
    // any valid index >= 0 clears the sign bit).
    if ((pidx.x & pidx.y & pidx.z & pidx.w) < 0) {
        const float4 z4 = make_float4(0.f, 0.f, 0.f, 0.f);
#pragma unroll
        for (int c = 0; c < CD; c++) {
            *reinterpret_cast<float4*>(outp + (size_t)c * PLANE) = z4;
        }
    } else {
        bool v0 = pidx.x >= 0, v1 = pidx.y >= 0, v2 = pidx.z >= 0, v3 = pidx.w >= 0;
        const float* r0 = pil + (size_t)(v0 ? pidx.x : 0) * CD;
        const float* r1 = pil + (size_t)(v1 ? pidx.y : 0) * CD;
        const float* r2 = pil + (size_t)(v2 ? pidx.z : 0) * CD;
        const float* r3 = pil + (size_t)(v3 ? pidx.w : 0) * CD;
#pragma unroll 8
        for (int c = 0; c < CD; c++) {
            float4 v;
            v.x = v0 ? __ldg(r0 + c) : 0.f;
            v.y = v1 ? __ldg(r1 + c) : 0.f;
            v.z = v2 ? __ldg(r2 + c) : 0.f;
            v.w = v3 ? __ldg(r3 + c) : 0.f;
            *reinterpret_cast<float4*>(outp + (size_t)c * PLANE) = v;
        }
    }
}

// ---------------------------------------------------------------------------
// Launch. Input order (metadata): pf0, vc0, pf1, vc1, pf2, vc2.
// Output: 3 canvases [4,64,496,432] f32 concatenated.
// ---------------------------------------------------------------------------
extern "C" void kernel_launch(void* const* d_in, const int* in_sizes, int n_in,
                              void* d_out, int out_size) {
    const float* pf0 = (const float*)d_in[0];
    const int*   vc0 = (const int*)  d_in[1];
    const float* pf1 = (const float*)d_in[2];
    const int*   vc1 = (const int*)  d_in[3];
    const float* pf2 = (const float*)d_in[4];
    const int*   vc2 = (const int*)  d_in[5];
    float* out = (float*)d_out;

    // 1) reset index canvas
    {
        int n4 = (NBB * PLANE) / 4;                 // 642816
        int threads = 256;
        int blocks = (n4 + threads - 1) / threads;
        init_idx_kernel<<<blocks, threads>>>();
    }
    // 2) scatter pillar indices
    {
        int n = NBINS * NPIL;                       // 192000
        int threads = 256;
        int blocks = (n + threads - 1) / threads;
        scatter_idx_kernel<<<blocks, threads>>>(vc0, vc1, vc2);
    }
    // 3) gather -> dense output
    {
        int Q = PLANE / 4;                          // 53568
        dim3 threads(256);
        dim3 blocks((Q + 255) / 256, NBB);          // (210, 12)
        gather_kernel<<<blocks, threads>>>(pf0, pf1, pf2, out);
    }
}